// round 11
// baseline (speedup 1.0000x reference)
#include <cuda_runtime.h>
#include <cuda_bf16.h>
#include <math.h>

#define SS     16      // samples per group
#define CC     128     // channels
#define GNN    256     // groups per batch item
#define NR     9       // max instance rows (bg + 8 fg labels)
#define GP     2       // groups per CTA
#define CPAD   129     // padded channel pitch in staged smem
#define NTHR   256
#define FXSCALE 1073741824.0f   // 2^30 fixed-point scale

// deterministic fixed-point accumulators (integer adds are order-invariant)
__device__ unsigned long long g_sum_gl = 0ull;
__device__ unsigned long long g_sum_gv = 0ull;
__device__ unsigned           g_count  = 0u;

// triangle pair LUT: p -> (i, j), j <= i, p = i(i+1)/2 + j, for instnum <= 9
__device__ __constant__ signed char TRI_I[45] = {
    0, 1,1, 2,2,2, 3,3,3,3, 4,4,4,4,4, 5,5,5,5,5,5,
    6,6,6,6,6,6,6, 7,7,7,7,7,7,7,7, 8,8,8,8,8,8,8,8,8 };
__device__ __constant__ signed char TRI_J[45] = {
    0, 0,1, 0,1,2, 0,1,2,3, 0,1,2,3,4, 0,1,2,3,4,5,
    0,1,2,3,4,5,6, 0,1,2,3,4,5,6,7, 0,1,2,3,4,5,6,7,8 };

__global__ void __launch_bounds__(NTHR) proposal_clloss_group_kernel(
    const int*   __restrict__ labs,    // [G*S]
    const float* __restrict__ feats,   // [bs, C, Gn, S]
    const int*   __restrict__ idxs,    // [G*S]
    const float* __restrict__ ctx,     // [C]
    float*       __restrict__ out)     // [1]
{
    __shared__ float s_sf[GP * SS * CPAD];               // staged [gs][s][c]
    __shared__ __align__(16) float s_M[GP][NR][CC];      // instance-mean rows
    __shared__ float s_sim[GP][NR * NR];
    __shared__ int   s_order[GP][SS];                    // samples sorted by row
    __shared__ int   s_start[GP][NR];
    __shared__ int   s_end[GP][NR];
    __shared__ float s_inv[GP][NR];
    __shared__ int   s_instnum[GP];
    __shared__ int   s_hasbg[GP];
    __shared__ float s_res[GP];                          // gl*gv per group
    __shared__ float s_gv[GP];                           // gv per group

    const int tid   = threadIdx.x;
    const int warp  = tid >> 5;
    const int lane  = tid & 31;
    const int gbase = blockIdx.x * GP;

    // ----- issue coalesced feature loads early --------------------------
    // 2 adjacent groups: per channel c, GP*SS floats = 128 B contiguous,
    // 128-B aligned (g_in even). flat = c*8 + gs*4 + q; 1024 float4 total.
    const int    g_in = gbase % GNN;
    const size_t base = (size_t)(gbase - g_in) * (CC * SS) + (size_t)g_in * SS;

    float4 v[4];
    int    dst_c[4], dst_r[4];
    #pragma unroll
    for (int it = 0; it < 4; it++) {
        const int flat = it * NTHR + tid;
        const int c  = flat >> 3;
        const int r  = flat & 7;        // gs*4 + q
        dst_c[it] = c;
        dst_r[it] = r;
        const float* p = feats + base + (size_t)c * (GNN * SS)
                       + (r >> 2) * SS + (r & 3) * 4;
        v[it] = *reinterpret_cast<const float4*>(p);
    }
    const float ctx_c = __ldg(ctx + (tid & (CC - 1)));

    // ----- Phase A: per-group metadata, warp w handles group w ----------
    if (warp < GP) {
        const int g   = gbase + warp;
        const bool smp = (lane < SS);
        const int idx_v = smp ? idxs[g * SS + lane] : (0x40000000 + lane);
        const int lab_v = smp ? labs[g * SS + lane] : 0;

        const unsigned m_idx = __match_any_sync(0xffffffffu, idx_v);
        const bool first = ((m_idx & ((1u << lane) - 1u)) == 0u);
        const int u = __popc(__ballot_sync(0xffffffffu, first && smp));

        const bool valid  = smp && (lane < u);
        const int labcode = valid ? (lab_v + 1) : 31;   // 0..8 valid, 31 = none

        unsigned b[NR];
        int cnt[NR];
        #pragma unroll
        for (int vv = 0; vv < NR; vv++) {
            b[vv]   = __ballot_sync(0xffffffffu, labcode == vv);
            cnt[vv] = __popc(b[vv]);
        }
        unsigned pres = 0;
        #pragma unroll
        for (int vv = 0; vv < NR; vv++) pres |= (cnt[vv] ? 1u : 0u) << vv;
        int pr[NR + 1];
        pr[0] = 0;
        #pragma unroll
        for (int vv = 0; vv < NR; vv++) pr[vv + 1] = pr[vv] + cnt[vv];

        const int hasbg   = (int)(pres & 1u);
        const int instnum = __popc(pres >> 1) + 1;

        if (valid) {
            const int pos = pr[labcode] + __popc(b[labcode] & ((1u << lane) - 1u));
            s_order[warp][pos] = lane;
        }
        if (lane < NR) {
            s_start[warp][lane] = 0;
            s_end[warp][lane]   = 0;
            s_inv[warp][lane]   = 1.0f;
        }
        __syncwarp();
        if (lane < NR && cnt[lane] > 0) {
            const int r = (lane == 0) ? 0
                        : 1 + __popc((pres & ((1u << lane) - 1u)) >> 1);
            s_start[warp][r] = pr[lane];
            s_end[warp][r]   = pr[lane] + cnt[lane];
            s_inv[warp][r]   = 1.0f / (float)cnt[lane];
        }
        if (lane == 0) { s_instnum[warp] = instnum; s_hasbg[warp] = hasbg; }
    }

    // ----- stage features to smem (transposed [gs][s][c]) ----------------
    #pragma unroll
    for (int it = 0; it < 4; it++) {
        const int c  = dst_c[it];
        const int gs = dst_r[it] >> 2;
        const int q  = dst_r[it] & 3;
        float* d = s_sf + (gs * SS + q * 4) * CPAD + c;
        d[0 * CPAD] = v[it].x;
        d[1 * CPAD] = v[it].y;
        d[2 * CPAD] = v[it].z;
        d[3 * CPAD] = v[it].w;
    }
    __syncthreads();

    // ----- Phase B: per-channel instance means (segment gather) ----------
    {
        const int gs   = tid >> 7;        // 0..1
        const int c    = tid & (CC - 1);  // 0..127
        const int inum = s_instnum[gs];
        const float* fcol = s_sf + gs * SS * CPAD + c;
        for (int r = 0; r < inum; r++) {
            const int st = s_start[gs][r];
            const int en = s_end[gs][r];
            float x = 0.0f;
            for (int k = st; k < en; k++)
                x += fcol[s_order[gs][k] * CPAD];
            s_M[gs][r][c] = x * s_inv[gs][r];
        }
        if (!s_hasbg[gs])
            s_M[gs][0][c] = ctx_c;         // row 0 = context compensation
    }
    __syncthreads();

    // ----- Phase C: sim = (M M^T) / T  (4 warps per group, float4 LDS) ---
    {
        const int gs   = warp & 1;
        const int sub  = warp >> 1;         // 0..3
        const int inum = s_instnum[gs];
        const int P = inum * (inum + 1) / 2;
        for (int p = sub; p < P; p += 4) {
            const int i = TRI_I[p];
            const int j = TRI_J[p];
            const float4 a  = reinterpret_cast<const float4*>(s_M[gs][i])[lane];
            const float4 bb = reinterpret_cast<const float4*>(s_M[gs][j])[lane];
            float pa = a.x * bb.x + a.y * bb.y + a.z * bb.z + a.w * bb.w;
            #pragma unroll
            for (int o = 16; o; o >>= 1)
                pa += __shfl_xor_sync(0xffffffffu, pa, o);
            if (lane == 0) {
                const float x = pa * 5.0f;  // 1/T, T = 0.2
                s_sim[gs][i * NR + j] = x;
                s_sim[gs][j * NR + i] = x;
            }
        }
    }
    __syncthreads();

    // ----- Phase D: per-row logsumexp, group loss ------------------------
    if (warp < GP) {
        const int gs   = warp;
        const int inum = s_instnum[gs];
        float li = 0.0f;
        const int i = lane + 1;
        if (i < inum) {
            float mx = -3.402823466e38f;
            for (int j = 0; j < inum; j++)
                mx = fmaxf(mx, s_sim[gs][i * NR + j]);
            float sum = 0.0f;
            for (int j = 0; j < inum; j++)
                sum += __expf(s_sim[gs][i * NR + j] - mx);
            li = mx + __logf(sum) - s_sim[gs][i * NR + i];
        }
        #pragma unroll
        for (int o = 16; o; o >>= 1)
            li += __shfl_xor_sync(0xffffffffu, li, o);
        if (lane == 0) {
            const float gv = (inum >= 2) ? 1.0f : 0.0f;
            const float gl = (inum >= 2) ? li / (float)(inum - 1) : 0.0f;
            s_res[gs] = gl * gv;
            s_gv[gs]  = gv;
        }
    }
    __syncthreads();

    // ----- fused deterministic reduction (single thread per CTA) ---------
    if (tid == 0) {
        const float a = s_res[0] + s_res[1];
        const float b = s_gv[0] + s_gv[1];
        // 2^30 fixed point: integer atomics commute exactly -> deterministic
        atomicAdd(&g_sum_gl,
                  (unsigned long long)(long long)llrintf(a * FXSCALE));
        atomicAdd(&g_sum_gv, (unsigned long long)(long long)b);
        __threadfence();                     // order value adds before counter
        const unsigned old = atomicAdd(&g_count, 1u);
        if (old == gridDim.x - 1) {          // last CTA finalizes
            __threadfence();
            const long long sg = (long long)atomicAdd(&g_sum_gl, 0ull);
            const long long sv = (long long)atomicAdd(&g_sum_gv, 0ull);
            out[0] = (float)(((double)sg / (double)FXSCALE)
                             / (double)sv * 0.1);
            g_sum_gl = 0ull;                 // self-reset for graph replay
            g_sum_gv = 0ull;
            g_count  = 0u;
        }
    }
}

extern "C" void kernel_launch(void* const* d_in, const int* in_sizes, int n_in,
                              void* d_out, int out_size)
{
    const int*   labs  = (const int*)  d_in[0];  // proposal_instance_mask [bs,Gn,S]
    const float* feats = (const float*)d_in[1];  // grouped_features [bs,C,Gn,S]
    const int*   idxs  = (const int*)  d_in[2];  // grouped_indices [bs,Gn,S]
    const float* ctx   = (const float*)d_in[3];  // context_compen [1,C]
    float*       out   = (float*)d_out;

    const int G = in_sizes[0] / SS;              // total group count (8192)

    proposal_clloss_group_kernel<<<G / GP, NTHR>>>(labs, feats, idxs, ctx, out);
}